// round 14
// baseline (speedup 1.0000x reference)
#include <cuda_runtime.h>
#include <cuda_fp16.h>
#include <mma.h>
#include <math.h>

using namespace nvcuda;

#define NN 12288
#define EE 393216
#define ET (EE + NN)
#define EW 96   // ELL width (in-degree ~Poisson(32)+1; P(>95) ~ 1e-14)

// ---------------- scratch (static __device__, no allocs; zero-initialized) ----------------
__device__ int   g_tmp[NN];          // slot counter during build; = deg+1 after; re-zeroed by last spmm
__device__ int   g_cidx[NN * EW];
__device__ float g_cval[NN * EW];

__device__ float g_P1[NN * 68];    // [x@W1 (64) | s=1-2x0 | pad(3)]
__device__ float g_H1[NN * 128];   // [relu(agg+b1) | relu(agg + t*W1row0 + b1)]
__device__ float g_Q [NN * 96];    // [H1a@W2 (64) | H1b@W2[:, :32]]
__device__ float g_ZS[NN * 96];    // z split: [z_s | z_ns | z_s_cf]
__device__ float g_AZ[NN * 96];    // agg of ZS
__device__ float g_HD[NN * 192];   // [relu d1(z_s) | relu d2(z_ns) | relu d1(z_s_cf)]
__device__ float g_AH[NN * 192];   // agg of HD
__device__ __half g_Hh[NN * 64];   // hs in fp16 (SYRK panel)

// ---------------- graph build: ONE atomic pass, then value fill from g_tmp --------------
__global__ void k_build(const int* __restrict__ ei) {
    int i = blockIdx.x * blockDim.x + threadIdx.x;
    if (i < EE) {
        int s = ei[i], d = ei[EE + i];
        int slot = atomicAdd(&g_tmp[d], 1);
        g_cidx[d * EW + slot] = s;
    } else if (i < ET) {
        int nid = i - EE;
        int slot = atomicAdd(&g_tmp[nid], 1);
        g_cidx[nid * EW + slot] = nid;
    }
}

__global__ __launch_bounds__(256) void k_val(void) {
    int warp = (blockIdx.x * blockDim.x + threadIdx.x) >> 5;
    int lane = threadIdx.x & 31;
    if (warp >= NN) return;
    int cnt = g_tmp[warp];
    float rd = rsqrtf((float)cnt);
    for (int p = lane; p < cnt; p += 32) {
        int s = g_cidx[warp * EW + p];
        g_cval[warp * EW + p] = rd * rsqrtf((float)g_tmp[s]);
    }
}

// ---------------- ELL SpMM, float4-vectorized (1 LDG.128 per lane per edge) -------------
// epi: 0 none, 1 z-split (also write e1=o_zs/e2=o_zns), 2 final (re-zero g_tmp),
//      3 encoder-L1 dual-branch (NSEG=17; e1 = W1 row 0; out 128-wide [H1a|H1b]),
//      4 AZ + fused structure head (NSEG=24; e1 = s_W, e2 = s_b; writes g_Hh fp16 panel)
template <int NSEG>
__global__ __launch_bounds__(256) void k_spmm(const float* __restrict__ H, int Fh,
                                              float* __restrict__ out, int Fo,
                                              const float* __restrict__ bias,
                                              int relu, int epi,
                                              const float* __restrict__ e1,
                                              float* __restrict__ e2) {
    const int NJ = (NSEG + 31) / 32;
    __shared__ float sw[32 * 64];   // s_W staging (epi==4 only)
    if (epi == 4) {
        for (int i = threadIdx.x; i < 32 * 64; i += 256) sw[i] = e1[i];
        __syncthreads();
    }

    int warp = (blockIdx.x * blockDim.x + threadIdx.x) >> 5;
    int lane = threadIdx.x & 31;
    if (warp >= NN) return;
    float4 acc[NJ];
#pragma unroll
    for (int j = 0; j < NJ; j++) acc[j] = make_float4(0.f, 0.f, 0.f, 0.f);
    int cnt = g_tmp[warp];
    const int*   ci = g_cidx + warp * EW;
    const float* cv = g_cval + warp * EW;
    int p = 0;
    for (; p + 2 <= cnt; p += 2) {
        int s0 = ci[p], s1 = ci[p + 1];
        float v0 = cv[p], v1 = cv[p + 1];
        const float4* h0 = (const float4*)(H + s0 * Fh);
        const float4* h1 = (const float4*)(H + s1 * Fh);
#pragma unroll
        for (int j = 0; j < NJ; j++) {
            int seg = lane + j * 32;
            if (seg < NSEG) {
                float4 a = __ldg(h0 + seg);
                float4 b = __ldg(h1 + seg);
                acc[j].x += v0 * a.x + v1 * b.x;
                acc[j].y += v0 * a.y + v1 * b.y;
                acc[j].z += v0 * a.z + v1 * b.z;
                acc[j].w += v0 * a.w + v1 * b.w;
            }
        }
    }
    if (p < cnt) {
        int s0 = ci[p];
        float v0 = cv[p];
        const float4* h0 = (const float4*)(H + s0 * Fh);
#pragma unroll
        for (int j = 0; j < NJ; j++) {
            int seg = lane + j * 32;
            if (seg < NSEG) {
                float4 a = __ldg(h0 + seg);
                acc[j].x += v0 * a.x;
                acc[j].y += v0 * a.y;
                acc[j].z += v0 * a.z;
                acc[j].w += v0 * a.w;
            }
        }
    }

    if (epi == 3) {
        // lane 16 (seg 16) holds aggregated s in .x; broadcast
        float t = __shfl_sync(0xffffffffu, acc[0].x, 16);
        int seg = lane;
        if (seg < 16) {
            float4 r = acc[0];
            float4 bv = *(const float4*)(bias + seg * 4);
            float4 w0 = *(const float4*)(e1 + seg * 4);    // W1 row 0
            float4 r1, r2;
            r1.x = fmaxf(r.x + bv.x, 0.f);
            r1.y = fmaxf(r.y + bv.y, 0.f);
            r1.z = fmaxf(r.z + bv.z, 0.f);
            r1.w = fmaxf(r.w + bv.w, 0.f);
            r2.x = fmaxf(r.x + t * w0.x + bv.x, 0.f);
            r2.y = fmaxf(r.y + t * w0.y + bv.y, 0.f);
            r2.z = fmaxf(r.z + t * w0.z + bv.z, 0.f);
            r2.w = fmaxf(r.w + t * w0.w + bv.w, 0.f);
            *(float4*)(out + warp * 128 + seg * 4) = r1;
            *(float4*)(out + warp * 128 + 64 + seg * 4) = r2;
        }
        return;
    }

    if (epi == 4) {
        // write AZ (no bias/relu)
        if (lane < NSEG) *(float4*)(out + warp * Fo + lane * 4) = acc[0];
        // fused structure head: hs = aggz_ns @ s_W + s_b  (aggz_ns = cols 32..63 = lanes 8..15)
        float h0 = e2[lane], h1 = e2[32 + lane];
#pragma unroll
        for (int q = 0; q < 8; q++) {
            float4 v;
            v.x = __shfl_sync(0xffffffffu, acc[0].x, 8 + q);
            v.y = __shfl_sync(0xffffffffu, acc[0].y, 8 + q);
            v.z = __shfl_sync(0xffffffffu, acc[0].z, 8 + q);
            v.w = __shfl_sync(0xffffffffu, acc[0].w, 8 + q);
            int k = q * 4;
            h0 += v.x * sw[k * 64 + lane]      + v.y * sw[(k + 1) * 64 + lane]
                + v.z * sw[(k + 2) * 64 + lane] + v.w * sw[(k + 3) * 64 + lane];
            h1 += v.x * sw[k * 64 + 32 + lane]      + v.y * sw[(k + 1) * 64 + 32 + lane]
                + v.z * sw[(k + 2) * 64 + 32 + lane] + v.w * sw[(k + 3) * 64 + 32 + lane];
        }
        g_Hh[warp * 64 + lane]      = __float2half_rn(h0);
        g_Hh[warp * 64 + 32 + lane] = __float2half_rn(h1);
        return;
    }

#pragma unroll
    for (int j = 0; j < NJ; j++) {
        int seg = lane + j * 32;
        if (seg < NSEG) {
            float4 r = acc[j];
            if (bias) {
                float4 bv = *(const float4*)(bias + ((seg * 4) & 63));
                r.x += bv.x; r.y += bv.y; r.z += bv.z; r.w += bv.w;
            }
            if (relu) {
                r.x = fmaxf(r.x, 0.f); r.y = fmaxf(r.y, 0.f);
                r.z = fmaxf(r.z, 0.f); r.w = fmaxf(r.w, 0.f);
            }
            *(float4*)(out + warp * Fo + seg * 4) = r;
            if (epi == 1) {
                if (seg < 8)       *(float4*)(e2 + warp * 32 + seg * 4) = r;           // o_zs
                else if (seg < 16) *(float4*)(e2 + NN * 32 + warp * 32 + (seg - 8) * 4) = r; // o_zns
            }
        }
    }
    if (epi == 2 && lane == 0) g_tmp[warp] = 0;
}

// ---------------- batched small GEMM ----------------
// cfdup==2: also write C[row*ldc+64] = 1-2*A[row,0]  (scalar s column for enc L1)
struct GemmOp {
    const float* A; int lda; int aoff;
    const float* B; int ldb;
    float*       C; int ldc; int coff;
    const float* bias;
    int relu; int nclip; int cfdup; int split;
};
struct GemmBatch { GemmOp op[4]; };

__global__ __launch_bounds__(256) void k_gemmb(GemmBatch ops, int K) {
    __shared__ float As[128 * 36];
    __shared__ float Bs[32 * 64];
    const GemmOp& P = ops.op[blockIdx.z];
    const float* A = P.A;
    int lda = P.lda, aoff = P.aoff;
    int r0 = blockIdx.x * 128;
    int c0 = blockIdx.y * 64;
    int t = threadIdx.x;
    int tx = t & 15, ty = t >> 4;
    float acc[8][4];
#pragma unroll
    for (int i = 0; i < 8; i++)
#pragma unroll
        for (int j = 0; j < 4; j++) acc[i][j] = 0.f;

    for (int kt = 0; kt < K; kt += 32) {
#pragma unroll
        for (int it = 0; it < 4; ++it) {
            int li = t + it * 256;
            int m = li >> 3;
            int kv = (li & 7) << 2;
            float4 v = *(const float4*)(A + (r0 + m) * lda + aoff + kt + kv);
            *(float4*)&As[m * 36 + kv] = v;
        }
#pragma unroll
        for (int it = 0; it < 2; ++it) {
            int li = t + it * 256;
            int kk = li >> 4;
            int nv = (li & 15) << 2;
            float4 v = *(const float4*)(P.B + (kt + kk) * P.ldb + c0 + nv);
            *(float4*)&Bs[kk * 64 + nv] = v;
        }
        __syncthreads();
#pragma unroll
        for (int k4 = 0; k4 < 32; k4 += 4) {
            float4 a4[8];
#pragma unroll
            for (int i = 0; i < 8; i++) a4[i] = *(const float4*)&As[(ty * 8 + i) * 36 + k4];
#pragma unroll
            for (int kk = 0; kk < 4; kk++) {
                float4 b = *(const float4*)&Bs[(k4 + kk) * 64 + tx * 4];
#pragma unroll
                for (int i = 0; i < 8; i++) {
                    float av = (kk == 0) ? a4[i].x : (kk == 1) ? a4[i].y : (kk == 2) ? a4[i].z : a4[i].w;
                    acc[i][0] += av * b.x;
                    acc[i][1] += av * b.y;
                    acc[i][2] += av * b.z;
                    acc[i][3] += av * b.w;
                }
            }
        }
        __syncthreads();
    }

    if (c0 + tx * 4 >= P.nclip) return;

    float bv[4] = {0.f, 0.f, 0.f, 0.f};
    if (P.bias) {
#pragma unroll
        for (int j = 0; j < 4; j++) bv[j] = P.bias[c0 + tx * 4 + j];
    }

#pragma unroll
    for (int i = 0; i < 8; i++) {
        int row = r0 + ty * 8 + i;
        float4 v;
        v.x = acc[i][0] + bv[0];
        v.y = acc[i][1] + bv[1];
        v.z = acc[i][2] + bv[2];
        v.w = acc[i][3] + bv[3];
        if (P.relu) {
            v.x = fmaxf(v.x, 0.f); v.y = fmaxf(v.y, 0.f);
            v.z = fmaxf(v.z, 0.f); v.w = fmaxf(v.w, 0.f);
        }
        *(float4*)(P.C + row * P.ldc + P.coff + c0 + tx * 4) = v;
        if (P.cfdup == 2 && tx == 0)
            P.C[row * P.ldc + 64] = 1.f - 2.f * A[row * lda];
    }
}

// ---------------- SYRK via fp16 tensor cores, SMEM-staged coalesced stores ----------------
#define SLD 72            // padded K stride (half elements)
#define SY_DSM (128 * 132 * 4)
__global__ __launch_bounds__(256) void k_syrk_tc(float* __restrict__ C) {
    extern __shared__ char dyn[];
    __half* As = (__half*)dyn;            // 128 x SLD
    __half* Bs = As + 128 * SLD;          // 128 x SLD
    float*  S  = (float*)dyn;             // 128 x 132 staging (aliases tiles)

    int t = blockIdx.x;
    float bf = 96.5f - sqrtf(96.5f * 96.5f - 2.0f * (float)t);
    int br = (int)bf;
    if (br < 0) br = 0;
    if (br > 95) br = 95;
    while (96 * br - (br * (br - 1)) / 2 > t) --br;
    while (96 * (br + 1) - ((br + 1) * br) / 2 <= t) ++br;
    int bc = br + (t - (96 * br - (br * (br - 1)) / 2));
    int r0 = br * 128, c0 = bc * 128;

    int tid = threadIdx.x;
#pragma unroll
    for (int it = 0; it < 4; ++it) {
        int li = tid + it * 256;           // 0..1023
        int row = li >> 3;
        int seg = li & 7;
        *(uint4*)&As[row * SLD + seg * 8] = *(const uint4*)&g_Hh[(r0 + row) * 64 + seg * 8];
        *(uint4*)&Bs[row * SLD + seg * 8] = *(const uint4*)&g_Hh[(c0 + row) * 64 + seg * 8];
    }
    __syncthreads();

    int w = tid >> 5;
    int wr = w >> 2;          // 0..1  -> 64-row slab
    int wc = w & 3;           // 0..3  -> 32-col slab

    wmma::fragment<wmma::accumulator, 16, 16, 16, float> acc[4][2];
#pragma unroll
    for (int i = 0; i < 4; i++)
#pragma unroll
        for (int j = 0; j < 2; j++) wmma::fill_fragment(acc[i][j], 0.f);

#pragma unroll
    for (int k = 0; k < 4; ++k) {
        wmma::fragment<wmma::matrix_a, 16, 16, 16, __half, wmma::row_major> af[4];
        wmma::fragment<wmma::matrix_b, 16, 16, 16, __half, wmma::col_major> bfv[2];
#pragma unroll
        for (int i = 0; i < 4; i++)
            wmma::load_matrix_sync(af[i], As + (wr * 64 + 16 * i) * SLD + k * 16, SLD);
#pragma unroll
        for (int j = 0; j < 2; j++)
            wmma::load_matrix_sync(bfv[j], Bs + (wc * 32 + 16 * j) * SLD + k * 16, SLD);
#pragma unroll
        for (int i = 0; i < 4; i++)
#pragma unroll
            for (int j = 0; j < 2; j++)
                wmma::mma_sync(acc[i][j], af[i], bfv[j], acc[i][j]);
    }
    __syncthreads();   // tiles fully consumed; staging may overwrite

    // pass 1: direct tile
#pragma unroll
    for (int i = 0; i < 4; i++)
#pragma unroll
        for (int j = 0; j < 2; j++)
            wmma::store_matrix_sync(S + (wr * 64 + 16 * i) * 132 + (wc * 32 + 16 * j),
                                    acc[i][j], 132, wmma::mem_row_major);
    __syncthreads();
    for (int i = tid; i < 128 * 32; i += 256) {
        int row = i >> 5, q = i & 31;
        float4 v = *(const float4*)&S[row * 132 + q * 4];
        *(float4*)(C + (size_t)(r0 + row) * NN + c0 + q * 4) = v;
    }

    // pass 2: mirrored tile (stage col-major => transpose), coalesced stores
    if (br != bc) {
        __syncthreads();
#pragma unroll
        for (int i = 0; i < 4; i++)
#pragma unroll
            for (int j = 0; j < 2; j++)
                wmma::store_matrix_sync(S + (wc * 32 + 16 * j) * 132 + (wr * 64 + 16 * i),
                                        acc[i][j], 132, wmma::mem_col_major);
        __syncthreads();
        for (int i = tid; i < 128 * 32; i += 256) {
            int row = i >> 5, q = i & 31;
            float4 v = *(const float4*)&S[row * 132 + q * 4];
            *(float4*)(C + (size_t)(c0 + row) * NN + r0 + q * 4) = v;
        }
    }
}

// ---------------- launch ----------------
extern "C" void kernel_launch(void* const* d_in, const int* in_sizes, int n_in,
                              void* d_out, int out_size) {
    const float* x      = (const float*)d_in[0];
    const int*   ei     = (const int*)d_in[1];
    const float* enc_W1 = (const float*)d_in[2];
    const float* enc_b1 = (const float*)d_in[3];
    const float* enc_W2 = (const float*)d_in[4];
    const float* enc_b2 = (const float*)d_in[5];
    const float* d1_W1  = (const float*)d_in[6];
    const float* d1_b1  = (const float*)d_in[7];
    const float* d1_W2  = (const float*)d_in[8];
    const float* d1_b2  = (const float*)d_in[9];
    const float* d2_W1  = (const float*)d_in[10];
    const float* d2_b1  = (const float*)d_in[11];
    const float* d2_W2  = (const float*)d_in[12];
    const float* d2_b2  = (const float*)d_in[13];
    const float* s_W    = (const float*)d_in[14];
    const float* s_b    = (const float*)d_in[15];

    float* out     = (float*)d_out;
    float* o_zs    = out;
    float* o_xs    = out + NN * 64;
    float* o_xns   = o_xs + NN * 256;
    float* o_xscf  = o_xns + NN * 256;
    float* o_s     = o_xscf + NN * 256;

    float *p_P1, *p_H1, *p_Q, *p_ZS, *p_AZ, *p_HD, *p_AH;
    cudaGetSymbolAddress((void**)&p_P1, g_P1);
    cudaGetSymbolAddress((void**)&p_H1, g_H1);
    cudaGetSymbolAddress((void**)&p_Q,  g_Q);
    cudaGetSymbolAddress((void**)&p_ZS, g_ZS);
    cudaGetSymbolAddress((void**)&p_AZ, g_AZ);
    cudaGetSymbolAddress((void**)&p_HD, g_HD);
    cudaGetSymbolAddress((void**)&p_AH, g_AH);

    cudaFuncSetAttribute(k_syrk_tc, cudaFuncAttributeMaxDynamicSharedMemorySize, SY_DSM);

    static cudaStream_t s1 = nullptr;
    static cudaEvent_t evF0, evJ0, evF1, evJ1;
    if (!s1) {
        cudaStreamCreateWithFlags(&s1, cudaStreamNonBlocking);
        cudaEventCreateWithFlags(&evF0, cudaEventDisableTiming);
        cudaEventCreateWithFlags(&evJ0, cudaEventDisableTiming);
        cudaEventCreateWithFlags(&evF1, cudaEventDisableTiming);
        cudaEventCreateWithFlags(&evJ1, cudaEventDisableTiming);
    }

    // ---- fork A: encoder layer-1 GEMM (68-wide, + scalar s column) on s1, || graph build
    cudaEventRecord(evF0, 0);
    cudaStreamWaitEvent(s1, evF0, 0);
    {
        GemmBatch gb{};
        gb.op[0] = { x, 256, 0, enc_W1, 64, p_P1, 68, 0, nullptr, 0, 64, 2, 0 };
        k_gemmb<<<dim3(96, 1, 1), 256, 0, s1>>>(gb, 256);
    }
    cudaEventRecord(evJ0, s1);

    // ---- stream 0: graph build (single-atomic ELL) + value fill ----
    k_build<<<(ET + 255) / 256, 256>>>(ei);
    k_val<<<NN / 8, 256>>>();
    cudaStreamWaitEvent(0, evJ0, 0);   // join A

    // encoder layer 1 aggregation: 65 useful cols (64 feat + scalar s), dual-branch epilogue
    k_spmm<17><<<NN / 8, 256>>>(p_P1, 68, p_H1, 128, enc_b1, 1, 3, enc_W1, nullptr);

    // encoder layer 2 projection: Q = [H1a@W2 | H1b@W2[:, :32]]
    {
        GemmBatch gb{};
        gb.op[0] = { p_H1, 128, 0,  enc_W2, 64, p_Q, 96, 0,  nullptr, 0, 64, 0, 0 };
        gb.op[1] = { p_H1, 128, 64, enc_W2, 64, p_Q, 96, 64, nullptr, 0, 32, 0, 0 };
        k_gemmb<<<dim3(96, 1, 2), 256>>>(gb, 64);
    }
    // z = agg(Q)+b2 (F=96) -> ZS = [z_s | z_ns | z_s_cf]; also o_zs/o_zns (via e2 = out base)
    k_spmm<24><<<NN / 8, 256>>>(p_Q, 96, p_ZS, 96, enc_b2, 0, 1, nullptr, o_zs);

    // aggregation of z-split (F=96) + FUSED structure head -> g_Hh fp16 panel
    k_spmm<24><<<NN / 8, 256>>>(p_ZS, 96, p_AZ, 96, nullptr, 0, 4, s_W, (float*)s_b);

    // ---- fork B: fp16 SYRK on s1, concurrent with decoder tail ----
    cudaEventRecord(evF1, 0);
    cudaStreamWaitEvent(s1, evF1, 0);
    k_syrk_tc<<<4656, 256, SY_DSM, s1>>>(o_s);
    cudaEventRecord(evJ1, s1);

    // decoder first convs (in SYRK shadow, stream 0)
    {
        GemmBatch gb{};
        gb.op[0] = { p_AZ, 96, 0,  d1_W1, 64, p_HD, 192, 0,   d1_b1, 1, 64, 0, 0 };
        gb.op[1] = { p_AZ, 96, 32, d2_W1, 64, p_HD, 192, 64,  d2_b1, 1, 64, 0, 0 };
        gb.op[2] = { p_AZ, 96, 64, d1_W1, 64, p_HD, 192, 128, d1_b1, 1, 64, 0, 0 };
        k_gemmb<<<dim3(96, 1, 3), 256>>>(gb, 32);
    }

    // decoder second convs (F=192; final epi re-zeroes g_tmp)
    k_spmm<48><<<NN / 8, 256>>>(p_HD, 192, p_AH, 192, nullptr, 0, 2, nullptr, nullptr);
    {
        GemmBatch gb{};
        gb.op[0] = { p_AH, 192, 0,   d1_W2, 256, o_xs,   256, 0, d1_b2, 0, 256, 0, 0 };
        gb.op[1] = { p_AH, 192, 64,  d2_W2, 256, o_xns,  256, 0, d2_b2, 0, 256, 0, 0 };
        gb.op[2] = { p_AH, 192, 128, d1_W2, 256, o_xscf, 256, 0, d1_b2, 0, 256, 0, 0 };
        k_gemmb<<<dim3(96, 4, 3), 256>>>(gb, 64);
    }

    cudaStreamWaitEvent(0, evJ1, 0);   // join B
}

// round 15
// speedup vs baseline: 1.0534x; 1.0534x over previous
#include <cuda_runtime.h>
#include <cuda_fp16.h>
#include <mma.h>
#include <math.h>

using namespace nvcuda;

#define NN 12288
#define EE 393216
#define ET (EE + NN)
#define EW 96   // ELL width (in-degree ~Poisson(32)+1; P(>95) ~ 1e-14)

// ---------------- scratch (static __device__, no allocs; zero-initialized) ----------------
__device__ int   g_tmp[NN];          // slot counter during build; = deg+1 after; re-zeroed by last spmm
__device__ int   g_cidx[NN * EW];
__device__ float g_cval[NN * EW];

__device__ float g_P1[NN * 68];    // [x@W1 (64) | s=1-2x0 | pad(3)]
__device__ float g_H1[NN * 128];   // [relu(agg+b1) | relu(agg + t*W1row0 + b1)]
__device__ float g_Q [NN * 96];    // [H1a@W2 (64) | H1b@W2[:, :32]]
__device__ float g_ZS[NN * 96];    // z split: [z_s | z_ns | z_s_cf]
__device__ float g_AZ[NN * 96];    // agg of ZS
__device__ float g_HD[NN * 192];   // [relu d1(z_s) | relu d2(z_ns) | relu d1(z_s_cf)]
__device__ float g_AH[NN * 192];   // agg of HD
__device__ __half g_Hh[NN * 64];   // hs in fp16 (SYRK panel)

// ---------------- graph build: ONE atomic pass, then value fill from g_tmp --------------
__global__ void k_build(const int* __restrict__ ei) {
    int i = blockIdx.x * blockDim.x + threadIdx.x;
    if (i < EE) {
        int s = ei[i], d = ei[EE + i];
        int slot = atomicAdd(&g_tmp[d], 1);
        g_cidx[d * EW + slot] = s;
    } else if (i < ET) {
        int nid = i - EE;
        int slot = atomicAdd(&g_tmp[nid], 1);
        g_cidx[nid * EW + slot] = nid;
    }
}

__global__ __launch_bounds__(256) void k_val(void) {
    int warp = (blockIdx.x * blockDim.x + threadIdx.x) >> 5;
    int lane = threadIdx.x & 31;
    if (warp >= NN) return;
    int cnt = g_tmp[warp];
    float rd = rsqrtf((float)cnt);
    for (int p = lane; p < cnt; p += 32) {
        int s = g_cidx[warp * EW + p];
        g_cval[warp * EW + p] = rd * rsqrtf((float)g_tmp[s]);
    }
}

// ---------------- ELL SpMM, float4-vectorized (1 LDG.128 per lane per edge) -------------
// epi: 0 none, 1 z-split (also write e1=o_zs/e2=o_zns), 2 final (re-zero g_tmp),
//      3 encoder-L1 dual-branch (NSEG=17; e1 = W1 row 0; out 128-wide [H1a|H1b])
template <int NSEG>
__global__ __launch_bounds__(256) void k_spmm(const float* __restrict__ H, int Fh,
                                              float* __restrict__ out, int Fo,
                                              const float* __restrict__ bias,
                                              int relu, int epi,
                                              float* __restrict__ e1,
                                              float* __restrict__ e2) {
    const int NJ = (NSEG + 31) / 32;
    int warp = (blockIdx.x * blockDim.x + threadIdx.x) >> 5;
    int lane = threadIdx.x & 31;
    if (warp >= NN) return;
    float4 acc[NJ];
#pragma unroll
    for (int j = 0; j < NJ; j++) acc[j] = make_float4(0.f, 0.f, 0.f, 0.f);
    int cnt = g_tmp[warp];
    const int*   ci = g_cidx + warp * EW;
    const float* cv = g_cval + warp * EW;
    int p = 0;
    for (; p + 2 <= cnt; p += 2) {
        int s0 = ci[p], s1 = ci[p + 1];
        float v0 = cv[p], v1 = cv[p + 1];
        const float4* h0 = (const float4*)(H + s0 * Fh);
        const float4* h1 = (const float4*)(H + s1 * Fh);
#pragma unroll
        for (int j = 0; j < NJ; j++) {
            int seg = lane + j * 32;
            if (seg < NSEG) {
                float4 a = __ldg(h0 + seg);
                float4 b = __ldg(h1 + seg);
                acc[j].x += v0 * a.x + v1 * b.x;
                acc[j].y += v0 * a.y + v1 * b.y;
                acc[j].z += v0 * a.z + v1 * b.z;
                acc[j].w += v0 * a.w + v1 * b.w;
            }
        }
    }
    if (p < cnt) {
        int s0 = ci[p];
        float v0 = cv[p];
        const float4* h0 = (const float4*)(H + s0 * Fh);
#pragma unroll
        for (int j = 0; j < NJ; j++) {
            int seg = lane + j * 32;
            if (seg < NSEG) {
                float4 a = __ldg(h0 + seg);
                acc[j].x += v0 * a.x;
                acc[j].y += v0 * a.y;
                acc[j].z += v0 * a.z;
                acc[j].w += v0 * a.w;
            }
        }
    }

    if (epi == 3) {
        // lane 16 (seg 16) holds aggregated s in .x; broadcast
        float t = __shfl_sync(0xffffffffu, acc[0].x, 16);
        int seg = lane;
        if (seg < 16) {
            float4 r = acc[0];
            float4 bv = *(const float4*)(bias + seg * 4);
            float4 w0 = *(const float4*)(e1 + seg * 4);    // W1 row 0
            float4 r1, r2;
            r1.x = fmaxf(r.x + bv.x, 0.f);
            r1.y = fmaxf(r.y + bv.y, 0.f);
            r1.z = fmaxf(r.z + bv.z, 0.f);
            r1.w = fmaxf(r.w + bv.w, 0.f);
            r2.x = fmaxf(r.x + t * w0.x + bv.x, 0.f);
            r2.y = fmaxf(r.y + t * w0.y + bv.y, 0.f);
            r2.z = fmaxf(r.z + t * w0.z + bv.z, 0.f);
            r2.w = fmaxf(r.w + t * w0.w + bv.w, 0.f);
            *(float4*)(out + warp * 128 + seg * 4) = r1;
            *(float4*)(out + warp * 128 + 64 + seg * 4) = r2;
        }
        return;
    }

#pragma unroll
    for (int j = 0; j < NJ; j++) {
        int seg = lane + j * 32;
        if (seg < NSEG) {
            float4 r = acc[j];
            if (bias) {
                float4 bv = *(const float4*)(bias + ((seg * 4) & 63));
                r.x += bv.x; r.y += bv.y; r.z += bv.z; r.w += bv.w;
            }
            if (relu) {
                r.x = fmaxf(r.x, 0.f); r.y = fmaxf(r.y, 0.f);
                r.z = fmaxf(r.z, 0.f); r.w = fmaxf(r.w, 0.f);
            }
            *(float4*)(out + warp * Fo + seg * 4) = r;
            if (epi == 1) {
                if (seg < 8)       *(float4*)(e1 + warp * 32 + seg * 4) = r;
                else if (seg < 16) *(float4*)(e2 + warp * 32 + (seg - 8) * 4) = r;
            }
        }
    }
    if (epi == 2 && lane == 0) g_tmp[warp] = 0;
}

// ---------------- batched small GEMM ----------------
// cfdup==2: also write C[row*ldc+64] = 1-2*A[row,0]  (scalar s column for enc L1)
// split: write fp16 SYRK panel g_Hh instead of C
struct GemmOp {
    const float* A; int lda; int aoff;
    const float* B; int ldb;
    float*       C; int ldc; int coff;
    const float* bias;
    int relu; int nclip; int cfdup; int split;
};
struct GemmBatch { GemmOp op[4]; };

__global__ __launch_bounds__(256) void k_gemmb(GemmBatch ops, int K) {
    __shared__ float As[128 * 36];
    __shared__ float Bs[32 * 64];
    const GemmOp& P = ops.op[blockIdx.z];
    const float* A = P.A;
    int lda = P.lda, aoff = P.aoff;
    int r0 = blockIdx.x * 128;
    int c0 = blockIdx.y * 64;
    int t = threadIdx.x;
    int tx = t & 15, ty = t >> 4;
    float acc[8][4];
#pragma unroll
    for (int i = 0; i < 8; i++)
#pragma unroll
        for (int j = 0; j < 4; j++) acc[i][j] = 0.f;

    for (int kt = 0; kt < K; kt += 32) {
#pragma unroll
        for (int it = 0; it < 4; ++it) {
            int li = t + it * 256;
            int m = li >> 3;
            int kv = (li & 7) << 2;
            float4 v = *(const float4*)(A + (r0 + m) * lda + aoff + kt + kv);
            *(float4*)&As[m * 36 + kv] = v;
        }
#pragma unroll
        for (int it = 0; it < 2; ++it) {
            int li = t + it * 256;
            int kk = li >> 4;
            int nv = (li & 15) << 2;
            float4 v = *(const float4*)(P.B + (kt + kk) * P.ldb + c0 + nv);
            *(float4*)&Bs[kk * 64 + nv] = v;
        }
        __syncthreads();
#pragma unroll
        for (int k4 = 0; k4 < 32; k4 += 4) {
            float4 a4[8];
#pragma unroll
            for (int i = 0; i < 8; i++) a4[i] = *(const float4*)&As[(ty * 8 + i) * 36 + k4];
#pragma unroll
            for (int kk = 0; kk < 4; kk++) {
                float4 b = *(const float4*)&Bs[(k4 + kk) * 64 + tx * 4];
#pragma unroll
                for (int i = 0; i < 8; i++) {
                    float av = (kk == 0) ? a4[i].x : (kk == 1) ? a4[i].y : (kk == 2) ? a4[i].z : a4[i].w;
                    acc[i][0] += av * b.x;
                    acc[i][1] += av * b.y;
                    acc[i][2] += av * b.z;
                    acc[i][3] += av * b.w;
                }
            }
        }
        __syncthreads();
    }

    if (c0 + tx * 4 >= P.nclip) return;

    float bv[4] = {0.f, 0.f, 0.f, 0.f};
    if (P.bias) {
#pragma unroll
        for (int j = 0; j < 4; j++) bv[j] = P.bias[c0 + tx * 4 + j];
    }

    if (P.split) {
#pragma unroll
        for (int i = 0; i < 8; i++) {
            int row = r0 + ty * 8 + i;
            __half2 h0 = __floats2half2_rn(acc[i][0] + bv[0], acc[i][1] + bv[1]);
            __half2 h1 = __floats2half2_rn(acc[i][2] + bv[2], acc[i][3] + bv[3]);
            *(__half2*)&g_Hh[row * 64 + c0 + tx * 4]     = h0;
            *(__half2*)&g_Hh[row * 64 + c0 + tx * 4 + 2] = h1;
        }
        return;
    }

#pragma unroll
    for (int i = 0; i < 8; i++) {
        int row = r0 + ty * 8 + i;
        float4 v;
        v.x = acc[i][0] + bv[0];
        v.y = acc[i][1] + bv[1];
        v.z = acc[i][2] + bv[2];
        v.w = acc[i][3] + bv[3];
        if (P.relu) {
            v.x = fmaxf(v.x, 0.f); v.y = fmaxf(v.y, 0.f);
            v.z = fmaxf(v.z, 0.f); v.w = fmaxf(v.w, 0.f);
        }
        *(float4*)(P.C + row * P.ldc + P.coff + c0 + tx * 4) = v;
        if (P.cfdup == 2 && tx == 0)
            P.C[row * P.ldc + 64] = 1.f - 2.f * A[row * lda];
    }
}

// ---------------- SYRK via fp16 tensor cores, SMEM-staged coalesced stores ----------------
#define SLD 72            // padded K stride (half elements)
#define SY_DSM (128 * 132 * 4)
__global__ __launch_bounds__(256) void k_syrk_tc(float* __restrict__ C) {
    extern __shared__ char dyn[];
    __half* As = (__half*)dyn;            // 128 x SLD
    __half* Bs = As + 128 * SLD;          // 128 x SLD
    float*  S  = (float*)dyn;             // 128 x 132 staging (aliases tiles)

    int t = blockIdx.x;
    float bf = 96.5f - sqrtf(96.5f * 96.5f - 2.0f * (float)t);
    int br = (int)bf;
    if (br < 0) br = 0;
    if (br > 95) br = 95;
    while (96 * br - (br * (br - 1)) / 2 > t) --br;
    while (96 * (br + 1) - ((br + 1) * br) / 2 <= t) ++br;
    int bc = br + (t - (96 * br - (br * (br - 1)) / 2));
    int r0 = br * 128, c0 = bc * 128;

    int tid = threadIdx.x;
#pragma unroll
    for (int it = 0; it < 4; ++it) {
        int li = tid + it * 256;           // 0..1023
        int row = li >> 3;
        int seg = li & 7;
        *(uint4*)&As[row * SLD + seg * 8] = *(const uint4*)&g_Hh[(r0 + row) * 64 + seg * 8];
        *(uint4*)&Bs[row * SLD + seg * 8] = *(const uint4*)&g_Hh[(c0 + row) * 64 + seg * 8];
    }
    __syncthreads();

    int w = tid >> 5;
    int wr = w >> 2;          // 0..1  -> 64-row slab
    int wc = w & 3;           // 0..3  -> 32-col slab

    wmma::fragment<wmma::accumulator, 16, 16, 16, float> acc[4][2];
#pragma unroll
    for (int i = 0; i < 4; i++)
#pragma unroll
        for (int j = 0; j < 2; j++) wmma::fill_fragment(acc[i][j], 0.f);

#pragma unroll
    for (int k = 0; k < 4; ++k) {
        wmma::fragment<wmma::matrix_a, 16, 16, 16, __half, wmma::row_major> af[4];
        wmma::fragment<wmma::matrix_b, 16, 16, 16, __half, wmma::col_major> bfv[2];
#pragma unroll
        for (int i = 0; i < 4; i++)
            wmma::load_matrix_sync(af[i], As + (wr * 64 + 16 * i) * SLD + k * 16, SLD);
#pragma unroll
        for (int j = 0; j < 2; j++)
            wmma::load_matrix_sync(bfv[j], Bs + (wc * 32 + 16 * j) * SLD + k * 16, SLD);
#pragma unroll
        for (int i = 0; i < 4; i++)
#pragma unroll
            for (int j = 0; j < 2; j++)
                wmma::mma_sync(acc[i][j], af[i], bfv[j], acc[i][j]);
    }
    __syncthreads();   // tiles fully consumed; staging may overwrite

    // pass 1: direct tile
#pragma unroll
    for (int i = 0; i < 4; i++)
#pragma unroll
        for (int j = 0; j < 2; j++)
            wmma::store_matrix_sync(S + (wr * 64 + 16 * i) * 132 + (wc * 32 + 16 * j),
                                    acc[i][j], 132, wmma::mem_row_major);
    __syncthreads();
    for (int i = tid; i < 128 * 32; i += 256) {
        int row = i >> 5, q = i & 31;
        float4 v = *(const float4*)&S[row * 132 + q * 4];
        *(float4*)(C + (size_t)(r0 + row) * NN + c0 + q * 4) = v;
    }

    // pass 2: mirrored tile (stage col-major => transpose), coalesced stores
    if (br != bc) {
        __syncthreads();
#pragma unroll
        for (int i = 0; i < 4; i++)
#pragma unroll
            for (int j = 0; j < 2; j++)
                wmma::store_matrix_sync(S + (wc * 32 + 16 * j) * 132 + (wr * 64 + 16 * i),
                                        acc[i][j], 132, wmma::mem_col_major);
        __syncthreads();
        for (int i = tid; i < 128 * 32; i += 256) {
            int row = i >> 5, q = i & 31;
            float4 v = *(const float4*)&S[row * 132 + q * 4];
            *(float4*)(C + (size_t)(c0 + row) * NN + r0 + q * 4) = v;
        }
    }
}

// ---------------- launch ----------------
extern "C" void kernel_launch(void* const* d_in, const int* in_sizes, int n_in,
                              void* d_out, int out_size) {
    const float* x      = (const float*)d_in[0];
    const int*   ei     = (const int*)d_in[1];
    const float* enc_W1 = (const float*)d_in[2];
    const float* enc_b1 = (const float*)d_in[3];
    const float* enc_W2 = (const float*)d_in[4];
    const float* enc_b2 = (const float*)d_in[5];
    const float* d1_W1  = (const float*)d_in[6];
    const float* d1_b1  = (const float*)d_in[7];
    const float* d1_W2  = (const float*)d_in[8];
    const float* d1_b2  = (const float*)d_in[9];
    const float* d2_W1  = (const float*)d_in[10];
    const float* d2_b1  = (const float*)d_in[11];
    const float* d2_W2  = (const float*)d_in[12];
    const float* d2_b2  = (const float*)d_in[13];
    const float* s_W    = (const float*)d_in[14];
    const float* s_b    = (const float*)d_in[15];

    float* out     = (float*)d_out;
    float* o_zs    = out;
    float* o_zns   = out + NN * 32;
    float* o_xs    = out + NN * 64;
    float* o_xns   = o_xs + NN * 256;
    float* o_xscf  = o_xns + NN * 256;
    float* o_s     = o_xscf + NN * 256;

    float *p_P1, *p_H1, *p_Q, *p_ZS, *p_AZ, *p_HD, *p_AH;
    cudaGetSymbolAddress((void**)&p_P1, g_P1);
    cudaGetSymbolAddress((void**)&p_H1, g_H1);
    cudaGetSymbolAddress((void**)&p_Q,  g_Q);
    cudaGetSymbolAddress((void**)&p_ZS, g_ZS);
    cudaGetSymbolAddress((void**)&p_AZ, g_AZ);
    cudaGetSymbolAddress((void**)&p_HD, g_HD);
    cudaGetSymbolAddress((void**)&p_AH, g_AH);

    cudaFuncSetAttribute(k_syrk_tc, cudaFuncAttributeMaxDynamicSharedMemorySize, SY_DSM);

    static cudaStream_t s1 = nullptr;
    static cudaEvent_t evF0, evJ0, evF1, evJ1;
    if (!s1) {
        cudaStreamCreateWithFlags(&s1, cudaStreamNonBlocking);
        cudaEventCreateWithFlags(&evF0, cudaEventDisableTiming);
        cudaEventCreateWithFlags(&evJ0, cudaEventDisableTiming);
        cudaEventCreateWithFlags(&evF1, cudaEventDisableTiming);
        cudaEventCreateWithFlags(&evJ1, cudaEventDisableTiming);
    }

    // ---- fork A: encoder layer-1 GEMM (68-wide, + scalar s column) on s1, || graph build
    cudaEventRecord(evF0, 0);
    cudaStreamWaitEvent(s1, evF0, 0);
    {
        GemmBatch gb{};
        gb.op[0] = { x, 256, 0, enc_W1, 64, p_P1, 68, 0, nullptr, 0, 64, 2, 0 };
        k_gemmb<<<dim3(96, 1, 1), 256, 0, s1>>>(gb, 256);
    }
    cudaEventRecord(evJ0, s1);

    // ---- stream 0: graph build (single-atomic ELL) + value fill ----
    k_build<<<(ET + 255) / 256, 256>>>(ei);
    k_val<<<NN / 8, 256>>>();
    cudaStreamWaitEvent(0, evJ0, 0);   // join A

    // encoder layer 1 aggregation: 65 useful cols (64 feat + scalar s), dual-branch epilogue
    k_spmm<17><<<NN / 8, 256>>>(p_P1, 68, p_H1, 128, enc_b1, 1, 3, (float*)enc_W1, nullptr);

    // encoder layer 2 projection: Q = [H1a@W2 | H1b@W2[:, :32]]
    {
        GemmBatch gb{};
        gb.op[0] = { p_H1, 128, 0,  enc_W2, 64, p_Q, 96, 0,  nullptr, 0, 64, 0, 0 };
        gb.op[1] = { p_H1, 128, 64, enc_W2, 64, p_Q, 96, 64, nullptr, 0, 32, 0, 0 };
        k_gemmb<<<dim3(96, 1, 2), 256>>>(gb, 64);
    }
    // z = agg(Q)+b2 (F=96) -> ZS = [z_s | z_ns | z_s_cf]; also o_zs/o_zns
    k_spmm<24><<<NN / 8, 256>>>(p_Q, 96, p_ZS, 96, enc_b2, 0, 1, o_zs, o_zns);

    // aggregation of z-split (F=96)
    k_spmm<24><<<NN / 8, 256>>>(p_ZS, 96, p_AZ, 96, nullptr, 0, 0, nullptr, nullptr);

    // decoder first convs + structure head (s_W op writes fp16 SYRK panel directly)
    {
        GemmBatch gb{};
        gb.op[0] = { p_AZ, 96, 0,  d1_W1, 64, p_HD, 192, 0,   d1_b1, 1, 64, 0, 0 };
        gb.op[1] = { p_AZ, 96, 32, d2_W1, 64, p_HD, 192, 64,  d2_b1, 1, 64, 0, 0 };
        gb.op[2] = { p_AZ, 96, 64, d1_W1, 64, p_HD, 192, 128, d1_b1, 1, 64, 0, 0 };
        gb.op[3] = { p_AZ, 96, 32, s_W,   64, nullptr, 0, 0,  s_b,   0, 64, 0, 1 };
        k_gemmb<<<dim3(96, 1, 4), 256>>>(gb, 32);
    }

    // ---- fork B: fp16 SYRK on s1, concurrent with decoder tail ----
    cudaEventRecord(evF1, 0);
    cudaStreamWaitEvent(s1, evF1, 0);
    k_syrk_tc<<<4656, 256, SY_DSM, s1>>>(o_s);
    cudaEventRecord(evJ1, s1);

    // decoder second convs (F=192; final epi re-zeroes g_tmp)
    k_spmm<48><<<NN / 8, 256>>>(p_HD, 192, p_AH, 192, nullptr, 0, 2, nullptr, nullptr);
    {
        GemmBatch gb{};
        gb.op[0] = { p_AH, 192, 0,   d1_W2, 256, o_xs,   256, 0, d1_b2, 0, 256, 0, 0 };
        gb.op[1] = { p_AH, 192, 64,  d2_W2, 256, o_xns,  256, 0, d2_b2, 0, 256, 0, 0 };
        gb.op[2] = { p_AH, 192, 128, d1_W2, 256, o_xscf, 256, 0, d1_b2, 0, 256, 0, 0 };
        k_gemmb<<<dim3(96, 4, 3), 256>>>(gb, 64);
    }

    cudaStreamWaitEvent(0, evJ1, 0);   // join B
}